// round 10
// baseline (speedup 1.0000x reference)
#include <cuda_runtime.h>
#include <cuda_fp16.h>
#include <cstdint>

#define N_NODES 50000
#define E_EDGES 1600000
#define NTILES  (E_EDGES / 128)   // 12500 exact
#define NBLK    ((N_NODES + 1023) / 1024)   // 49

#define NODE_BLKS 782    // ceil(50000/64)
#define HIST_BLKS 6250   // E/256
#define INITV_BLKS 6250  // N*128/4 elems / 256 thr
#define PRE_BLKS (NODE_BLKS + HIST_BLKS + INITV_BLKS)

// ---------------- device scratch ----------------
__device__ float    g_t[(size_t)N_NODES * 128];     // x@W1a + b1 (fp32)
__device__ unsigned g_seg[(size_t)N_NODES * 128];   // order-preserving max
__device__ unsigned g_hist[N_NODES];                // invariant: zero at kernel_launch entry
__device__ unsigned g_cursor[N_NODES];
__device__ unsigned g_bsum[64];
__device__ int      g_er[E_EDGES];                  // rows, sorted by col
__device__ int      g_ec[E_EDGES];                  // cols, sorted

#define SENT 0x007FFFFFu   // fmap(-inf)

__device__ __forceinline__ unsigned fmap(float f) {
    unsigned u = __float_as_uint(f);
    return (u & 0x80000000u) ? ~u : (u | 0x80000000u);
}
__device__ __forceinline__ float funmap(unsigned u) {
    return __uint_as_float((u & 0x80000000u) ? (u ^ 0x80000000u) : ~u);
}
__device__ __forceinline__ void mma_fp16(float* d, const uint32_t* a, uint32_t b0, uint32_t b1) {
    asm volatile("mma.sync.aligned.m16n8k16.row.col.f32.f16.f16.f32 "
        "{%0,%1,%2,%3}, {%4,%5,%6,%7}, {%8,%9}, {%0,%1,%2,%3};"
        : "+f"(d[0]), "+f"(d[1]), "+f"(d[2]), "+f"(d[3])
        : "r"(a[0]), "r"(a[1]), "r"(a[2]), "r"(a[3]), "r"(b0), "r"(b1));
}
__device__ __forceinline__ uint32_t packh2(float a, float b) {
    __half2 h = __floats2half2_rn(a, b);
    return *(uint32_t*)&h;
}
__device__ __forceinline__ uint32_t smem_u32(const void* p) {
    uint32_t a;
    asm("{ .reg .u64 t; cvta.to.shared.u64 t, %1; cvt.u32.u64 %0, t; }" : "=r"(a) : "l"(p));
    return a;
}
__device__ __forceinline__ void ldsm_x4(uint32_t* r, uint32_t addr) {
    asm volatile("ldmatrix.sync.aligned.m8n8.x4.shared.b16 {%0,%1,%2,%3}, [%4];"
        : "=r"(r[0]), "=r"(r[1]), "=r"(r[2]), "=r"(r[3]) : "r"(addr));
}

// ---------------------------------------------------------------------------
// pre_kernel  LAUNCH #1: node GEMM | edge-dst histogram | g_seg init
// ---------------------------------------------------------------------------
__global__ void __launch_bounds__(256) pre_kernel(
    const float* __restrict__ x, const float* __restrict__ W1,
    const float* __restrict__ b1, const float* __restrict__ Wr,
    const float* __restrict__ br, float* __restrict__ out,
    const int* __restrict__ ei)
{
    int tid = threadIdx.x;
    int b   = blockIdx.x;

    if (b >= NODE_BLKS) {
        if (b < NODE_BLKS + HIST_BLKS) {
            int e = (b - NODE_BLKS) * 256 + tid;
            if (e < E_EDGES) atomicAdd(&g_hist[ei[E_EDGES + e]], 1u);
        } else {
            int i = (b - NODE_BLKS - HIST_BLKS) * 256 + tid;   // uint4 index
            uint4 s = make_uint4(SENT, SENT, SENT, SENT);
            ((uint4*)g_seg)[i] = s;
        }
        return;
    }

    extern __shared__ float sm[];
    float* sX = sm;
    float* sB = sm + 64 * 128;
    int base = b * 64;

#pragma unroll
    for (int i = 0; i < 8; i++) {
        int idx = tid + 256 * i, row = idx >> 5, c4 = idx & 31;
        float4 v = make_float4(0.f, 0.f, 0.f, 0.f);
        int node = base + row;
        if (node < N_NODES) v = *(const float4*)(x + (size_t)node * 128 + c4 * 4);
        *(float4*)(sX + row * 128 + c4 * 4) = v;
    }
    float acc[8][8];
#pragma unroll
    for (int i = 0; i < 8; i++)
#pragma unroll
        for (int j = 0; j < 8; j++) acc[i][j] = 0.f;

    int rt = tid >> 5, ct = tid & 31;
    for (int kc = 0; kc < 8; kc++) {
        __syncthreads();
#pragma unroll
        for (int i = 0; i < 4; i++) {
            int f = tid + 256 * i, kk = f >> 6, c = (f & 63) * 4, k = kc * 16 + kk;
            float4 v;
            if (c < 128) v = *(const float4*)(W1 + k * 128 + c);
            else         v = *(const float4*)(Wr + k * 128 + (c - 128));
            *(float4*)(sB + kk * 256 + c) = v;
        }
        __syncthreads();
#pragma unroll
        for (int kk = 0; kk < 16; kk++) {
            int k = kc * 16 + kk;
            float a[8];
#pragma unroll
            for (int i = 0; i < 8; i++) a[i] = sX[(rt * 8 + i) * 128 + k];
            float4 b0 = *(const float4*)(sB + kk * 256 + ct * 8);
            float4 b1v = *(const float4*)(sB + kk * 256 + ct * 8 + 4);
            float bb[8] = {b0.x, b0.y, b0.z, b0.w, b1v.x, b1v.y, b1v.z, b1v.w};
#pragma unroll
            for (int i = 0; i < 8; i++)
#pragma unroll
                for (int j = 0; j < 8; j++) acc[i][j] = fmaf(a[i], bb[j], acc[i][j]);
        }
    }
#pragma unroll
    for (int i = 0; i < 8; i++) {
        int node = base + rt * 8 + i;
        if (node >= N_NODES) continue;
#pragma unroll
        for (int j = 0; j < 8; j++) {
            int c = ct * 8 + j;
            if (c < 128) g_t[(size_t)node * 128 + c] = acc[i][j] + __ldg(b1 + c);
            else out[(size_t)node * 128 + (c - 128)] = acc[i][j] + __ldg(br + c - 128);
        }
    }
}

// block-local exclusive scan; re-zeroes g_hist        LAUNCH #2
__global__ void scan1_kernel() {
    __shared__ unsigned s[1024];
    int tid = threadIdx.x;
    int gid = blockIdx.x * 1024 + tid;
    unsigned v = (gid < N_NODES) ? g_hist[gid] : 0u;
    s[tid] = v; __syncthreads();
    for (int off = 1; off < 1024; off <<= 1) {
        unsigned t = (tid >= off) ? s[tid - off] : 0u;
        __syncthreads();
        s[tid] += t;
        __syncthreads();
    }
    if (gid < N_NODES) {
        g_cursor[gid] = s[tid] - v;
        g_hist[gid] = 0u;
    }
    if (tid == 1023) g_bsum[blockIdx.x] = s[1023];
}

// scatter with local bsum scan                        LAUNCH #3
__global__ void scatter_kernel(const int* __restrict__ ei) {
    __shared__ unsigned sB[64];
    int tid = threadIdx.x;
    if (tid < NBLK) sB[tid] = g_bsum[tid];
    __syncthreads();
    if (tid == 0) {
        unsigned c = 0;
#pragma unroll 1
        for (int b = 0; b < NBLK; b++) { unsigned t = sB[b]; sB[b] = c; c += t; }
    }
    __syncthreads();
    int e = blockIdx.x * blockDim.x + tid;
    if (e < E_EDGES) {
        int c = ei[E_EDGES + e];
        unsigned p = atomicAdd(&g_cursor[c], 1u) + sB[c >> 10];
        g_er[p] = ei[e];
        g_ec[p] = c;
    }
}

// ---------------------------------------------------------------------------
// edge kernel: 256 thr, 2 CTAs/SM, 64x32 warp tiles, sC aliased over sT
//                                                     LAUNCH #4  <-- PROFILED
// ---------------------------------------------------------------------------
#define W1P_F  0                    // 384 floats
#define COL_F  384                  // 128 ints
#define SB_F   512                  // 8192 floats (uint2 B fragments)
#define SC_F   (SB_F + 8192)        // 8704: sC 128x129 fp32 (16512 floats)
                                    //        sT aliased at same base (8704 words)
#define EDGE_SMEM_F (SC_F + 16512)  // 25216 floats = 100864 B
#define EDGE_SMEM_BYTES (EDGE_SMEM_F * 4)

__global__ void __launch_bounds__(256, 2) edge_kernel(
    const float* __restrict__ pos, const float* __restrict__ W1,
    const float* __restrict__ W2, const float* __restrict__ b2g)
{
    extern __shared__ float sm[];
    float*    sW1p = sm + W1P_F;
    int*      sCol = (int*)(sm + COL_F);
    uint2*    sBf  = (uint2*)(sm + SB_F);
    float*    sC   = sm + SC_F;                  // [col][row] pitch 129 (epilogue on)
    uint32_t* sTw  = (uint32_t*)(sm + SC_F);     // fp16 A tile, pitch 68 words (ALIAS)

    int tid  = threadIdx.x;
    int wid  = tid >> 5;
    int lane = tid & 31;
    int q    = lane & 3;
    int nn   = lane >> 2;
    int wr   = wid & 1;      // row group: rows wr*64 .. +63
    int wc   = wid >> 1;     // col group: cols wc*32 .. +31

    // one-time: W2 fp16 fragments (same mapping as R8/R9), W1p
    for (int i = tid; i < 4096; i += 256) {
        int ln = i & 31, nbg = (i >> 5) & 15, s = i >> 9;
        int qq = ln & 3, nni = ln >> 2;
        int n = nbg * 8 + nni, k = s * 16 + qq * 2;
        uint2 v;
        v.x = packh2(W2[k * 128 + n],       W2[(k + 1) * 128 + n]);
        v.y = packh2(W2[(k + 8) * 128 + n], W2[(k + 9) * 128 + n]);
        sBf[i] = v;
    }
    for (int f = tid; f < 384; f += 256) sW1p[f] = W1[128 * 128 + f];

    // b2 in registers (cols this thread writes in epilogue)
    float b2r[8];
#pragma unroll
    for (int nb = 0; nb < 4; nb++) {
        b2r[nb * 2]     = __ldg(b2g + wc * 32 + nb * 8 + q * 2);
        b2r[nb * 2 + 1] = __ldg(b2g + wc * 32 + nb * 8 + q * 2 + 1);
    }
    __syncthreads();   // preload visible before stage(tile0)

    // ldmatrix per-lane base addresses (4 mb blocks of 16 rows)
    uint32_t stbase = smem_u32(sTw);
    int lrow = wr * 64 + (lane & 15);
    int lk   = (lane >> 4) << 3;
    uint32_t aAddr[4];
#pragma unroll
    for (int mb = 0; mb < 4; mb++)
        aAddr[mb] = stbase + (uint32_t)(((lrow + mb * 16) * 136 + lk) * 2);

    int srow = tid >> 1;     // row this thread stages (2 threads/row)
    int p    = tid & 1;      // interleaved float4 groups: j = 2m + p

    // ---- prologue: prefetch tile0 metadata ----
    int tile = blockIdx.x;
    int per = 0, pcol_r = 0;
    float rx = 0.f, ry = 0.f, rz = 0.f;
    {
        int pb = (tile < NTILES ? tile : 0) * 128;
        per = g_er[pb + srow];
        int pc = g_ec[pb + srow];
        rx = pos[3 * per    ] - pos[3 * pc    ];
        ry = pos[3 * per + 1] - pos[3 * pc + 1];
        rz = pos[3 * per + 2] - pos[3 * pc + 2];
        if (tid < 128) pcol_r = g_ec[pb + tid];
    }

    for (; tile < NTILES; tile += gridDim.x) {
        // ---- stage(t): g_t rows + rel.W1p -> fp16 sT (single quantization) ----
        {
            const float4* tp = (const float4*)(g_t + (size_t)per * 128);
#pragma unroll
            for (int m = 0; m < 16; m++) {
                int j = 2 * m + p;               // float4 group, k = 4j
                float4 v = tp[j];
                float4 wx = *(const float4*)(sW1p + 4 * j);
                float4 wy = *(const float4*)(sW1p + 128 + 4 * j);
                float4 wz = *(const float4*)(sW1p + 256 + 4 * j);
                float h0 = fmaxf(v.x + rx * wx.x + ry * wy.x + rz * wz.x, 0.f);
                float h1 = fmaxf(v.y + rx * wx.y + ry * wy.y + rz * wz.y, 0.f);
                float h2 = fmaxf(v.z + rx * wx.z + ry * wy.z + rz * wz.z, 0.f);
                float h3 = fmaxf(v.w + rx * wx.w + ry * wy.w + rz * wz.w, 0.f);
                uint2 o;
                o.x = packh2(h0, h1);
                o.y = packh2(h2, h3);
                *(uint2*)(sTw + srow * 68 + j * 2) = o;
            }
            if (tid < 128) sCol[tid] = pcol_r;
        }

        // ---- prefetch(t+1) scalars (hidden under GEMM) ----
        {
            int nt = tile + gridDim.x;
            int pb = (nt < NTILES ? nt : 0) * 128;
            per = g_er[pb + srow];
            int pc = g_ec[pb + srow];
            rx = pos[3 * per    ] - pos[3 * pc    ];
            ry = pos[3 * per + 1] - pos[3 * pc + 1];
            rz = pos[3 * per + 2] - pos[3 * pc + 2];
            if (tid < 128) pcol_r = g_ec[pb + tid];
        }
        __syncthreads();   // [A] sT/sCol visible

        // ---- GEMM(t): 8 k16-steps, warp tile 64x32 (4 mb x 4 nb) ----
        float acc[4][4][4];
#pragma unroll
        for (int mb = 0; mb < 4; mb++)
#pragma unroll
            for (int nb = 0; nb < 4; nb++)
#pragma unroll
                for (int r = 0; r < 4; r++) acc[mb][nb][r] = 0.f;

#pragma unroll
        for (int s = 0; s < 8; s++) {
            uint32_t A[4][4];
#pragma unroll
            for (int mb = 0; mb < 4; mb++) ldsm_x4(A[mb], aAddr[mb] + s * 32);
#pragma unroll
            for (int nb = 0; nb < 4; nb++) {
                uint2 bv = sBf[(s * 16 + wc * 4 + nb) * 32 + lane];
#pragma unroll
                for (int mb = 0; mb < 4; mb++)
                    mma_fp16(acc[mb][nb], A[mb], bv.x, bv.y);
            }
        }
        __syncthreads();   // [B] all ldmatrix reads of sT done (epi overwrites region)

        // ---- epilogue: acc -> sC transposed [col][row], +b2 ----
#pragma unroll
        for (int mb = 0; mb < 4; mb++) {
#pragma unroll
            for (int nb = 0; nb < 4; nb++) {
#pragma unroll
                for (int r = 0; r < 4; r++) {
                    int row = wr * 64 + mb * 16 + nn + ((r >> 1) ? 8 : 0);
                    int col = wc * 32 + nb * 8 + q * 2 + (r & 1);
                    sC[col * 129 + row] = acc[mb][nb][r] + b2r[nb * 2 + (r & 1)];
                }
            }
        }
        __syncthreads();   // [C] sC visible

        // ---- run-max(t): 2 segments of 64 rows, atomics at run boundaries ----
        {
            int col = tid & 127;
            int r0  = (tid >> 7) * 64;
            int curc = sCol[r0];
            float m = sC[col * 129 + r0];
#pragma unroll 4
            for (int r = r0 + 1; r < r0 + 64; r++) {
                int cn = sCol[r];
                float v = sC[col * 129 + r];
                if (cn != curc) {
                    atomicMax(&g_seg[(size_t)curc * 128 + col], fmap(m));
                    curc = cn; m = v;
                } else {
                    m = fmaxf(m, v);
                }
            }
            atomicMax(&g_seg[(size_t)curc * 128 + col], fmap(m));
        }
        __syncthreads();   // [D] sC reads done; next stage may overwrite region
    }
}

// ---------------------------------------------------------------------------
__global__ void finalize(float* __restrict__ out) {      // LAUNCH #5
    int i = blockIdx.x * blockDim.x + threadIdx.x;       // uint4 index
    if (i < N_NODES * 32) {
        uint4 u = ((const uint4*)g_seg)[i];
        float4 o = *(float4*)(out + 4 * i);
        o.x += (u.x == SENT) ? 0.f : funmap(u.x);
        o.y += (u.y == SENT) ? 0.f : funmap(u.y);
        o.z += (u.z == SENT) ? 0.f : funmap(u.z);
        o.w += (u.w == SENT) ? 0.f : funmap(u.w);
        *(float4*)(out + 4 * i) = o;
    }
}

// ---------------------------------------------------------------------------
extern "C" void kernel_launch(void* const* d_in, const int* in_sizes, int n_in,
                              void* d_out, int out_size)
{
    const float* x   = (const float*)d_in[0];
    const float* pos = (const float*)d_in[1];
    const int*   ei  = (const int*)  d_in[2];
    const float* W1  = (const float*)d_in[3];
    const float* b1  = (const float*)d_in[4];
    const float* W2  = (const float*)d_in[5];
    const float* b2  = (const float*)d_in[6];
    const float* Wr  = (const float*)d_in[7];
    const float* br  = (const float*)d_in[8];
    float* out = (float*)d_out;

    const int NODE_SMEM = (64 * 128 + 16 * 256) * 4;

    cudaFuncSetAttribute(pre_kernel,  cudaFuncAttributeMaxDynamicSharedMemorySize, NODE_SMEM);
    cudaFuncSetAttribute(edge_kernel, cudaFuncAttributeMaxDynamicSharedMemorySize, EDGE_SMEM_BYTES);

    int nsm = 148;
    cudaDeviceGetAttribute(&nsm, cudaDevAttrMultiProcessorCount, 0);

    pre_kernel<<<PRE_BLKS, 256, NODE_SMEM>>>(x, W1, b1, Wr, br, out, ei);   // 1
    scan1_kernel<<<NBLK, 1024>>>();                                          // 2
    scatter_kernel<<<(E_EDGES + 1023) / 1024, 1024>>>(ei);                   // 3
    edge_kernel<<<2 * nsm, 256, EDGE_SMEM_BYTES>>>(pos, W1, W2, b2);         // 4
    finalize<<<(N_NODES * 32 + 255) / 256, 256>>>(out);                      // 5
}

// round 12
// speedup vs baseline: 1.1336x; 1.1336x over previous
#include <cuda_runtime.h>
#include <cuda_fp16.h>
#include <cstdint>

#define N_NODES 50000
#define E_EDGES 1600000
#define NTILES  (E_EDGES / 128)   // 12500 exact
#define NBLK    ((N_NODES + 1023) / 1024)   // 49

#define NODE_BLKS 782    // ceil(50000/64)
#define HIST_BLKS 6250   // E/256
#define INITV_BLKS 6250  // N*128/4 elems / 256 thr
#define PRE_BLKS (NODE_BLKS + HIST_BLKS + INITV_BLKS)

// ---------------- device scratch ----------------
__device__ float    g_t[(size_t)N_NODES * 128];     // x@W1a + b1 (fp32)
__device__ unsigned g_seg[(size_t)N_NODES * 128];   // order-preserving max
__device__ unsigned g_hist[N_NODES];                // invariant: zero at kernel_launch entry
__device__ unsigned g_cursor[N_NODES];
__device__ unsigned g_bsum[64];
__device__ int      g_er[E_EDGES];                  // rows, sorted by col
__device__ int      g_ec[E_EDGES];                  // cols, sorted

#define SENT 0x007FFFFFu   // fmap(-inf)

__device__ __forceinline__ unsigned fmap(float f) {
    unsigned u = __float_as_uint(f);
    return (u & 0x80000000u) ? ~u : (u | 0x80000000u);
}
__device__ __forceinline__ float funmap(unsigned u) {
    return __uint_as_float((u & 0x80000000u) ? (u ^ 0x80000000u) : ~u);
}
__device__ __forceinline__ void mma_fp16(float* d, const uint32_t* a, uint32_t b0, uint32_t b1) {
    asm volatile("mma.sync.aligned.m16n8k16.row.col.f32.f16.f16.f32 "
        "{%0,%1,%2,%3}, {%4,%5,%6,%7}, {%8,%9}, {%0,%1,%2,%3};"
        : "+f"(d[0]), "+f"(d[1]), "+f"(d[2]), "+f"(d[3])
        : "r"(a[0]), "r"(a[1]), "r"(a[2]), "r"(a[3]), "r"(b0), "r"(b1));
}
__device__ __forceinline__ uint32_t packh2(float a, float b) {
    __half2 h = __floats2half2_rn(a, b);
    return *(uint32_t*)&h;
}
__device__ __forceinline__ uint32_t smem_u32(const void* p) {
    uint32_t a;
    asm("{ .reg .u64 t; cvta.to.shared.u64 t, %1; cvt.u32.u64 %0, t; }" : "=r"(a) : "l"(p));
    return a;
}
__device__ __forceinline__ void ldsm_x4(uint32_t* r, uint32_t addr) {
    asm volatile("ldmatrix.sync.aligned.m8n8.x4.shared.b16 {%0,%1,%2,%3}, [%4];"
        : "=r"(r[0]), "=r"(r[1]), "=r"(r[2]), "=r"(r[3]) : "r"(addr));
}

// ---------------------------------------------------------------------------
// pre_kernel  LAUNCH #1: node GEMM | edge-dst histogram | g_seg init
// ---------------------------------------------------------------------------
__global__ void __launch_bounds__(256) pre_kernel(
    const float* __restrict__ x, const float* __restrict__ W1,
    const float* __restrict__ b1, const float* __restrict__ Wr,
    const float* __restrict__ br, float* __restrict__ out,
    const int* __restrict__ ei)
{
    int tid = threadIdx.x;
    int b   = blockIdx.x;

    if (b >= NODE_BLKS) {
        if (b < NODE_BLKS + HIST_BLKS) {
            int e = (b - NODE_BLKS) * 256 + tid;
            if (e < E_EDGES) atomicAdd(&g_hist[ei[E_EDGES + e]], 1u);
        } else {
            int i = (b - NODE_BLKS - HIST_BLKS) * 256 + tid;   // uint4 index
            uint4 s = make_uint4(SENT, SENT, SENT, SENT);
            ((uint4*)g_seg)[i] = s;
        }
        return;
    }

    extern __shared__ float sm[];
    float* sX = sm;
    float* sB = sm + 64 * 128;
    int base = b * 64;

#pragma unroll
    for (int i = 0; i < 8; i++) {
        int idx = tid + 256 * i, row = idx >> 5, c4 = idx & 31;
        float4 v = make_float4(0.f, 0.f, 0.f, 0.f);
        int node = base + row;
        if (node < N_NODES) v = *(const float4*)(x + (size_t)node * 128 + c4 * 4);
        *(float4*)(sX + row * 128 + c4 * 4) = v;
    }
    float acc[8][8];
#pragma unroll
    for (int i = 0; i < 8; i++)
#pragma unroll
        for (int j = 0; j < 8; j++) acc[i][j] = 0.f;

    int rt = tid >> 5, ct = tid & 31;
    for (int kc = 0; kc < 8; kc++) {
        __syncthreads();
#pragma unroll
        for (int i = 0; i < 4; i++) {
            int f = tid + 256 * i, kk = f >> 6, c = (f & 63) * 4, k = kc * 16 + kk;
            float4 v;
            if (c < 128) v = *(const float4*)(W1 + k * 128 + c);
            else         v = *(const float4*)(Wr + k * 128 + (c - 128));
            *(float4*)(sB + kk * 256 + c) = v;
        }
        __syncthreads();
#pragma unroll
        for (int kk = 0; kk < 16; kk++) {
            int k = kc * 16 + kk;
            float a[8];
#pragma unroll
            for (int i = 0; i < 8; i++) a[i] = sX[(rt * 8 + i) * 128 + k];
            float4 b0 = *(const float4*)(sB + kk * 256 + ct * 8);
            float4 b1v = *(const float4*)(sB + kk * 256 + ct * 8 + 4);
            float bb[8] = {b0.x, b0.y, b0.z, b0.w, b1v.x, b1v.y, b1v.z, b1v.w};
#pragma unroll
            for (int i = 0; i < 8; i++)
#pragma unroll
                for (int j = 0; j < 8; j++) acc[i][j] = fmaf(a[i], bb[j], acc[i][j]);
        }
    }
#pragma unroll
    for (int i = 0; i < 8; i++) {
        int node = base + rt * 8 + i;
        if (node >= N_NODES) continue;
#pragma unroll
        for (int j = 0; j < 8; j++) {
            int c = ct * 8 + j;
            if (c < 128) g_t[(size_t)node * 128 + c] = acc[i][j] + __ldg(b1 + c);
            else out[(size_t)node * 128 + (c - 128)] = acc[i][j] + __ldg(br + c - 128);
        }
    }
}

// block-local exclusive scan; re-zeroes g_hist        LAUNCH #2
__global__ void scan1_kernel() {
    __shared__ unsigned s[1024];
    int tid = threadIdx.x;
    int gid = blockIdx.x * 1024 + tid;
    unsigned v = (gid < N_NODES) ? g_hist[gid] : 0u;
    s[tid] = v; __syncthreads();
    for (int off = 1; off < 1024; off <<= 1) {
        unsigned t = (tid >= off) ? s[tid - off] : 0u;
        __syncthreads();
        s[tid] += t;
        __syncthreads();
    }
    if (gid < N_NODES) {
        g_cursor[gid] = s[tid] - v;
        g_hist[gid] = 0u;
    }
    if (tid == 1023) g_bsum[blockIdx.x] = s[1023];
}

// scatter with local bsum scan                        LAUNCH #3
__global__ void scatter_kernel(const int* __restrict__ ei) {
    __shared__ unsigned sB[64];
    int tid = threadIdx.x;
    if (tid < NBLK) sB[tid] = g_bsum[tid];
    __syncthreads();
    if (tid == 0) {
        unsigned c = 0;
#pragma unroll 1
        for (int b = 0; b < NBLK; b++) { unsigned t = sB[b]; sB[b] = c; c += t; }
    }
    __syncthreads();
    int e = blockIdx.x * blockDim.x + tid;
    if (e < E_EDGES) {
        int c = ei[E_EDGES + e];
        unsigned p = atomicAdd(&g_cursor[c], 1u) + sB[c >> 10];
        g_er[p] = ei[e];
        g_ec[p] = c;
    }
}

// ---------------------------------------------------------------------------
// edge kernel (512 thr, software-pipelined, R9 structure)
//   ONLY CHANGE vs R9: sC pitch 129 -> 131 (write bank conflicts 4-way -> 2-way,
//   reads stay conflict-free since gcd(3,32)=1)
//                                                     LAUNCH #4  <-- PROFILED
// ---------------------------------------------------------------------------
#define SC_PITCH 131
#define W1P_F  0
#define B2_F   384
#define COLB_F 512                  // 2 x 128 (double-buffered)
#define SB_F   768                  // 8192 floats (uint2 fragments)
#define SC_F   (SB_F + 8192)        // 8960: 128 x 131 fp32 = 16768 floats
#define ST_F   (SC_F + 16768)       // 25728: fp16 128 x 136 halves = 8704 floats
#define EDGE_SMEM_F (ST_F + 8704)   // 34432 floats = 137728 B
#define EDGE_SMEM_BYTES (EDGE_SMEM_F * 4)

__global__ void __launch_bounds__(512, 1) edge_kernel(
    const float* __restrict__ pos, const float* __restrict__ W1,
    const float* __restrict__ W2, const float* __restrict__ b2)
{
    extern __shared__ float sm[];
    float*    sW1p  = sm + W1P_F;
    float*    sb2   = sm + B2_F;
    int*      sColB = (int*)(sm + COLB_F);
    uint2*    sBf   = (uint2*)(sm + SB_F);
    float*    sC    = sm + SC_F;                 // [col][row] pitch 131
    uint32_t* sTw   = (uint32_t*)(sm + ST_F);    // fp16 tile, pitch 68 words

    int tid  = threadIdx.x;
    int wid  = tid >> 5;
    int lane = tid & 31;
    int q    = lane & 3;
    int nn   = lane >> 2;
    int wr   = wid & 3;
    int wc   = wid >> 2;

    // one-time: W2 fp16 fragments, W1p, b2
    for (int i = tid; i < 4096; i += 512) {
        int ln = i & 31, nbg = (i >> 5) & 15, s = i >> 9;
        int qq = ln & 3, nni = ln >> 2;
        int n = nbg * 8 + nni, k = s * 16 + qq * 2;
        uint2 v;
        v.x = packh2(W2[k * 128 + n],       W2[(k + 1) * 128 + n]);
        v.y = packh2(W2[(k + 8) * 128 + n], W2[(k + 9) * 128 + n]);
        sBf[i] = v;
    }
    for (int f = tid; f < 384; f += 512) sW1p[f] = W1[128 * 128 + f];
    if (tid < 128) sb2[tid] = b2[tid];
    __syncthreads();   // preload visible before stage(tile0)

    // ldmatrix per-lane addresses
    uint32_t stbase = smem_u32(sTw);
    int lrow = wr * 32 + (lane & 15);
    int lk   = (lane >> 4) << 3;
    uint32_t aAddr0 = stbase + (uint32_t)((lrow       * 136 + lk) * 2);
    uint32_t aAddr1 = stbase + (uint32_t)(((lrow + 16) * 136 + lk) * 2);

    int rloc = wid * 8 + nn;                     // row this thread stages

    // ---- prologue: prefetch tile0 into regs (fp32) ----
    int tile = blockIdx.x;
    float4 R[8];
    float rx = 0.f, ry = 0.f, rz = 0.f;
    int pcol = 0;
    {
        int pb = (tile < NTILES ? tile : 0) * 128;
        int pr = g_er[pb + rloc];
        int pc = g_ec[pb + rloc];
        rx = pos[3 * pr    ] - pos[3 * pc    ];
        ry = pos[3 * pr + 1] - pos[3 * pc + 1];
        rz = pos[3 * pr + 2] - pos[3 * pc + 2];
        const float4* tp = (const float4*)(g_t + (size_t)pr * 128);
#pragma unroll
        for (int j = 0; j < 8; j++) R[j] = tp[j * 4 + q];
        if (tid < 128) pcol = g_ec[pb + tid];
    }

    int cur = 0;
    for (; tile < NTILES; tile += gridDim.x, cur ^= 1) {
        // ---- stage(t): regs -> sT (single fp16 quantization here) ----
#pragma unroll
        for (int j = 0; j < 8; j++) {
            float4 v = R[j];
            int kb = 16 * j + 4 * q;
            float4 wx = *(const float4*)(sW1p + kb);
            float4 wy = *(const float4*)(sW1p + 128 + kb);
            float4 wz = *(const float4*)(sW1p + 256 + kb);
            float h0 = fmaxf(v.x + rx * wx.x + ry * wy.x + rz * wz.x, 0.f);
            float h1 = fmaxf(v.y + rx * wx.y + ry * wy.y + rz * wz.y, 0.f);
            float h2 = fmaxf(v.z + rx * wx.z + ry * wy.z + rz * wz.z, 0.f);
            float h3 = fmaxf(v.w + rx * wx.w + ry * wy.w + rz * wz.w, 0.f);
            uint2 o;
            o.x = packh2(h0, h1);
            o.y = packh2(h2, h3);
            *(uint2*)(sTw + rloc * 68 + j * 8 + q * 2) = o;
        }
        if (tid < 128) sColB[cur * 128 + tid] = pcol;

        // ---- prefetch(t+1) -> regs (hidden under GEMM) ----
        {
            int nt = tile + gridDim.x;
            int pb = (nt < NTILES ? nt : 0) * 128;
            int pr = g_er[pb + rloc];
            int pc = g_ec[pb + rloc];
            rx = pos[3 * pr    ] - pos[3 * pc    ];
            ry = pos[3 * pr + 1] - pos[3 * pc + 1];
            rz = pos[3 * pr + 2] - pos[3 * pc + 2];
            const float4* tp = (const float4*)(g_t + (size_t)pr * 128);
#pragma unroll
            for (int j = 0; j < 8; j++) R[j] = tp[j * 4 + q];
            if (tid < 128) pcol = g_ec[pb + tid];
        }
        __syncthreads();   // [A] sT/sColB visible; sC free (run-max done)

        // ---- GEMM(t): 8 k16-steps, per warp 2 m16 x 4 n8 ----
        float acc[2][4][4];
#pragma unroll
        for (int mb = 0; mb < 2; mb++)
#pragma unroll
            for (int nb = 0; nb < 4; nb++)
#pragma unroll
                for (int r = 0; r < 4; r++) acc[mb][nb][r] = 0.f;

#pragma unroll
        for (int s = 0; s < 8; s++) {
            uint32_t A0[4], A1[4];
            ldsm_x4(A0, aAddr0 + s * 32);
            ldsm_x4(A1, aAddr1 + s * 32);
#pragma unroll
            for (int nb = 0; nb < 4; nb++) {
                uint2 bv = sBf[(s * 16 + wc * 4 + nb) * 32 + lane];
                mma_fp16(acc[0][nb], A0, bv.x, bv.y);
                mma_fp16(acc[1][nb], A1, bv.x, bv.y);
            }
        }

        // ---- epilogue: acc -> sC transposed, +b2 (pitch 131: <=2-way write) ----
#pragma unroll
        for (int mb = 0; mb < 2; mb++) {
#pragma unroll
            for (int nb = 0; nb < 4; nb++) {
#pragma unroll
                for (int r = 0; r < 4; r++) {
                    int row = wr * 32 + mb * 16 + nn + ((r >> 1) ? 8 : 0);
                    int col = wc * 32 + nb * 8 + q * 2 + (r & 1);
                    sC[col * SC_PITCH + row] = acc[mb][nb][r] + sb2[col];
                }
            }
        }
        __syncthreads();   // [B] sC visible; GEMM's sT reads done

        // ---- run-max(t) over sorted cols, 4 segs of 32 rows ----
        {
            const int* sCol = sColB + cur * 128;
            int col = tid & 127;
            int r0  = (tid >> 7) * 32;
            int curc = sCol[r0];
            float m = sC[col * SC_PITCH + r0];
#pragma unroll 4
            for (int r = r0 + 1; r < r0 + 32; r++) {
                int cn = sCol[r];
                float v = sC[col * SC_PITCH + r];
                if (cn != curc) {
                    atomicMax(&g_seg[(size_t)curc * 128 + col], fmap(m));
                    curc = cn; m = v;
                } else {
                    m = fmaxf(m, v);
                }
            }
            atomicMax(&g_seg[(size_t)curc * 128 + col], fmap(m));
        }
    }
}

// ---------------------------------------------------------------------------
__global__ void finalize(float* __restrict__ out) {      // LAUNCH #5
    int i = blockIdx.x * blockDim.x + threadIdx.x;       // uint4 index
    if (i < N_NODES * 32) {
        uint4 u = ((const uint4*)g_seg)[i];
        float4 o = *(float4*)(out + 4 * i);
        o.x += (u.x == SENT) ? 0.f : funmap(u.x);
        o.y += (u.y == SENT) ? 0.f : funmap(u.y);
        o.z += (u.z == SENT) ? 0.f : funmap(u.z);
        o.w += (u.w == SENT) ? 0.f : funmap(u.w);
        *(float4*)(out + 4 * i) = o;
    }
}

// ---------------------------------------------------------------------------
extern "C" void kernel_launch(void* const* d_in, const int* in_sizes, int n_in,
                              void* d_out, int out_size)
{
    const float* x   = (const float*)d_in[0];
    const float* pos = (const float*)d_in[1];
    const int*   ei  = (const int*)  d_in[2];
    const float* W1  = (const float*)d_in[3];
    const float* b1  = (const float*)d_in[4];
    const float* W2  = (const float*)d_in[5];
    const float* b2  = (const float*)d_in[6];
    const float* Wr  = (const float*)d_in[7];
    const float* br  = (const float*)d_in[8];
    float* out = (float*)d_out;

    const int NODE_SMEM = (64 * 128 + 16 * 256) * 4;

    cudaFuncSetAttribute(pre_kernel,  cudaFuncAttributeMaxDynamicSharedMemorySize, NODE_SMEM);
    cudaFuncSetAttribute(edge_kernel, cudaFuncAttributeMaxDynamicSharedMemorySize, EDGE_SMEM_BYTES);

    int nsm = 148;
    cudaDeviceGetAttribute(&nsm, cudaDevAttrMultiProcessorCount, 0);

    pre_kernel<<<PRE_BLKS, 256, NODE_SMEM>>>(x, W1, b1, Wr, br, out, ei);   // 1
    scan1_kernel<<<NBLK, 1024>>>();                                          // 2
    scatter_kernel<<<(E_EDGES + 1023) / 1024, 1024>>>(ei);                   // 3
    edge_kernel<<<nsm, 512, EDGE_SMEM_BYTES>>>(pos, W1, W2, b2);             // 4
    finalize<<<(N_NODES * 32 + 255) / 256, 256>>>(out);                      // 5
}

// round 14
// speedup vs baseline: 1.2188x; 1.0752x over previous
#include <cuda_runtime.h>
#include <cuda_fp16.h>
#include <cstdint>

#define N_NODES 50000
#define E_EDGES 1600000
#define NTILES  (E_EDGES / 128)   // 12500 exact
#define NBLK    ((N_NODES + 1023) / 1024)   // 49

#define NODE_BLKS 782    // ceil(50000/64)
#define HIST_BLKS 6250   // E/256
#define INITV_BLKS 6250  // N*128/4 elems / 256 thr
#define PRE_BLKS (NODE_BLKS + HIST_BLKS + INITV_BLKS)

// ---------------- device scratch ----------------
__device__ float    g_t[(size_t)N_NODES * 128];     // x@W1a + b1 (fp32)
__device__ unsigned g_seg[(size_t)N_NODES * 128];   // order-preserving max
__device__ unsigned g_hist[N_NODES];                // invariant: zero at kernel_launch entry
__device__ unsigned g_cursor[N_NODES];
__device__ unsigned g_bsum[64];
__device__ int      g_er[E_EDGES];                  // rows, sorted by col
__device__ int      g_ec[E_EDGES];                  // cols, sorted

#define SENT 0x007FFFFFu   // fmap(-inf)

__device__ __forceinline__ unsigned fmap(float f) {
    unsigned u = __float_as_uint(f);
    return (u & 0x80000000u) ? ~u : (u | 0x80000000u);
}
__device__ __forceinline__ float funmap(unsigned u) {
    return __uint_as_float((u & 0x80000000u) ? (u ^ 0x80000000u) : ~u);
}
__device__ __forceinline__ void mma_fp16(float* d, const uint32_t* a, uint32_t b0, uint32_t b1) {
    asm volatile("mma.sync.aligned.m16n8k16.row.col.f32.f16.f16.f32 "
        "{%0,%1,%2,%3}, {%4,%5,%6,%7}, {%8,%9}, {%0,%1,%2,%3};"
        : "+f"(d[0]), "+f"(d[1]), "+f"(d[2]), "+f"(d[3])
        : "r"(a[0]), "r"(a[1]), "r"(a[2]), "r"(a[3]), "r"(b0), "r"(b1));
}
__device__ __forceinline__ uint32_t packh2(float a, float b) {
    __half2 h = __floats2half2_rn(a, b);
    return *(uint32_t*)&h;
}
__device__ __forceinline__ uint32_t smem_u32(const void* p) {
    uint32_t a;
    asm("{ .reg .u64 t; cvta.to.shared.u64 t, %1; cvt.u32.u64 %0, t; }" : "=r"(a) : "l"(p));
    return a;
}
__device__ __forceinline__ void ldsm_x4(uint32_t* r, uint32_t addr) {
    asm volatile("ldmatrix.sync.aligned.m8n8.x4.shared.b16 {%0,%1,%2,%3}, [%4];"
        : "=r"(r[0]), "=r"(r[1]), "=r"(r[2]), "=r"(r[3]) : "r"(addr));
}

// ---------------------------------------------------------------------------
// pre_kernel  LAUNCH #1: node GEMM | edge-dst histogram | g_seg init
// ---------------------------------------------------------------------------
__global__ void __launch_bounds__(256) pre_kernel(
    const float* __restrict__ x, const float* __restrict__ W1,
    const float* __restrict__ b1, const float* __restrict__ Wr,
    const float* __restrict__ br, float* __restrict__ out,
    const int* __restrict__ ei)
{
    int tid = threadIdx.x;
    int b   = blockIdx.x;

    if (b >= NODE_BLKS) {
        if (b < NODE_BLKS + HIST_BLKS) {
            int e = (b - NODE_BLKS) * 256 + tid;
            if (e < E_EDGES) atomicAdd(&g_hist[ei[E_EDGES + e]], 1u);
        } else {
            int i = (b - NODE_BLKS - HIST_BLKS) * 256 + tid;   // uint4 index
            uint4 s = make_uint4(SENT, SENT, SENT, SENT);
            ((uint4*)g_seg)[i] = s;
        }
        return;
    }

    extern __shared__ float sm[];
    float* sX = sm;
    float* sB = sm + 64 * 128;
    int base = b * 64;

#pragma unroll
    for (int i = 0; i < 8; i++) {
        int idx = tid + 256 * i, row = idx >> 5, c4 = idx & 31;
        float4 v = make_float4(0.f, 0.f, 0.f, 0.f);
        int node = base + row;
        if (node < N_NODES) v = *(const float4*)(x + (size_t)node * 128 + c4 * 4);
        *(float4*)(sX + row * 128 + c4 * 4) = v;
    }
    float acc[8][8];
#pragma unroll
    for (int i = 0; i < 8; i++)
#pragma unroll
        for (int j = 0; j < 8; j++) acc[i][j] = 0.f;

    int rt = tid >> 5, ct = tid & 31;
    for (int kc = 0; kc < 8; kc++) {
        __syncthreads();
#pragma unroll
        for (int i = 0; i < 4; i++) {
            int f = tid + 256 * i, kk = f >> 6, c = (f & 63) * 4, k = kc * 16 + kk;
            float4 v;
            if (c < 128) v = *(const float4*)(W1 + k * 128 + c);
            else         v = *(const float4*)(Wr + k * 128 + (c - 128));
            *(float4*)(sB + kk * 256 + c) = v;
        }
        __syncthreads();
#pragma unroll
        for (int kk = 0; kk < 16; kk++) {
            int k = kc * 16 + kk;
            float a[8];
#pragma unroll
            for (int i = 0; i < 8; i++) a[i] = sX[(rt * 8 + i) * 128 + k];
            float4 b0 = *(const float4*)(sB + kk * 256 + ct * 8);
            float4 b1v = *(const float4*)(sB + kk * 256 + ct * 8 + 4);
            float bb[8] = {b0.x, b0.y, b0.z, b0.w, b1v.x, b1v.y, b1v.z, b1v.w};
#pragma unroll
            for (int i = 0; i < 8; i++)
#pragma unroll
                for (int j = 0; j < 8; j++) acc[i][j] = fmaf(a[i], bb[j], acc[i][j]);
        }
    }
#pragma unroll
    for (int i = 0; i < 8; i++) {
        int node = base + rt * 8 + i;
        if (node >= N_NODES) continue;
#pragma unroll
        for (int j = 0; j < 8; j++) {
            int c = ct * 8 + j;
            if (c < 128) g_t[(size_t)node * 128 + c] = acc[i][j] + __ldg(b1 + c);
            else out[(size_t)node * 128 + (c - 128)] = acc[i][j] + __ldg(br + c - 128);
        }
    }
}

// block-local exclusive scan; re-zeroes g_hist        LAUNCH #2
__global__ void scan1_kernel() {
    __shared__ unsigned s[1024];
    int tid = threadIdx.x;
    int gid = blockIdx.x * 1024 + tid;
    unsigned v = (gid < N_NODES) ? g_hist[gid] : 0u;
    s[tid] = v; __syncthreads();
    for (int off = 1; off < 1024; off <<= 1) {
        unsigned t = (tid >= off) ? s[tid - off] : 0u;
        __syncthreads();
        s[tid] += t;
        __syncthreads();
    }
    if (gid < N_NODES) {
        g_cursor[gid] = s[tid] - v;
        g_hist[gid] = 0u;
    }
    if (tid == 1023) g_bsum[blockIdx.x] = s[1023];
}

// scatter with local bsum scan                        LAUNCH #3
__global__ void scatter_kernel(const int* __restrict__ ei) {
    __shared__ unsigned sB[64];
    int tid = threadIdx.x;
    if (tid < NBLK) sB[tid] = g_bsum[tid];
    __syncthreads();
    if (tid == 0) {
        unsigned c = 0;
#pragma unroll 1
        for (int b = 0; b < NBLK; b++) { unsigned t = sB[b]; sB[b] = c; c += t; }
    }
    __syncthreads();
    int e = blockIdx.x * blockDim.x + tid;
    if (e < E_EDGES) {
        int c = ei[E_EDGES + e];
        unsigned p = atomicAdd(&g_cursor[c], 1u) + sB[c >> 10];
        g_er[p] = ei[e];
        g_ec[p] = c;
    }
}

// ---------------------------------------------------------------------------
// edge kernel (512 thr, software-pipelined)
//   R14: sC pitch 132 (epi stores conflict-free: bank = 8q+nn+const covers
//   0..31; float4 run-max reads 16B-aligned since 132 % 4 == 0 and
//   phase-disjoint since 4*col groups are disjoint), sCol via int4 broadcast.
//                                                     LAUNCH #4  <-- PROFILED
// ---------------------------------------------------------------------------
#define SC_PITCH 132
#define W1P_F  0
#define B2_F   384
#define COLB_F 512                  // 2 x 128 ints (double-buffered)
#define SB_F   768                  // 8192 floats (uint2 fragments)
#define SC_F   (SB_F + 8192)        // 8960: 128 x 132 fp32 = 16896 floats
#define ST_F   (SC_F + 16896)       // 25856: fp16 128 x 136 halves = 8704 floats
#define EDGE_SMEM_F (ST_F + 8704)   // 34560 floats = 138240 B
#define EDGE_SMEM_BYTES (EDGE_SMEM_F * 4)

__global__ void __launch_bounds__(512, 1) edge_kernel(
    const float* __restrict__ pos, const float* __restrict__ W1,
    const float* __restrict__ W2, const float* __restrict__ b2)
{
    extern __shared__ float sm[];
    float*    sW1p  = sm + W1P_F;
    float*    sb2   = sm + B2_F;
    int*      sColB = (int*)(sm + COLB_F);
    uint2*    sBf   = (uint2*)(sm + SB_F);
    float*    sC    = sm + SC_F;                 // [col][row] pitch 132
    uint32_t* sTw   = (uint32_t*)(sm + ST_F);    // fp16 tile, pitch 68 words

    int tid  = threadIdx.x;
    int wid  = tid >> 5;
    int lane = tid & 31;
    int q    = lane & 3;
    int nn   = lane >> 2;
    int wr   = wid & 3;
    int wc   = wid >> 2;

    // one-time: W2 fp16 fragments, W1p, b2
    for (int i = tid; i < 4096; i += 512) {
        int ln = i & 31, nbg = (i >> 5) & 15, s = i >> 9;
        int qq = ln & 3, nni = ln >> 2;
        int n = nbg * 8 + nni, k = s * 16 + qq * 2;
        uint2 v;
        v.x = packh2(W2[k * 128 + n],       W2[(k + 1) * 128 + n]);
        v.y = packh2(W2[(k + 8) * 128 + n], W2[(k + 9) * 128 + n]);
        sBf[i] = v;
    }
    for (int f = tid; f < 384; f += 512) sW1p[f] = W1[128 * 128 + f];
    if (tid < 128) sb2[tid] = b2[tid];
    __syncthreads();   // preload visible before stage(tile0)

    // ldmatrix per-lane addresses
    uint32_t stbase = smem_u32(sTw);
    int lrow = wr * 32 + (lane & 15);
    int lk   = (lane >> 4) << 3;
    uint32_t aAddr0 = stbase + (uint32_t)((lrow       * 136 + lk) * 2);
    uint32_t aAddr1 = stbase + (uint32_t)(((lrow + 16) * 136 + lk) * 2);

    int rloc = wid * 8 + nn;                     // row this thread stages

    // ---- prologue: prefetch tile0 into regs (fp32) ----
    int tile = blockIdx.x;
    float4 R[8];
    float rx = 0.f, ry = 0.f, rz = 0.f;
    int pcol = 0;
    {
        int pb = (tile < NTILES ? tile : 0) * 128;
        int pr = g_er[pb + rloc];
        int pc = g_ec[pb + rloc];
        rx = pos[3 * pr    ] - pos[3 * pc    ];
        ry = pos[3 * pr + 1] - pos[3 * pc + 1];
        rz = pos[3 * pr + 2] - pos[3 * pc + 2];
        const float4* tp = (const float4*)(g_t + (size_t)pr * 128);
#pragma unroll
        for (int j = 0; j < 8; j++) R[j] = tp[j * 4 + q];
        if (tid < 128) pcol = g_ec[pb + tid];
    }

    int cur = 0;
    for (; tile < NTILES; tile += gridDim.x, cur ^= 1) {
        // ---- stage(t): regs -> sT (single fp16 quantization here) ----
#pragma unroll
        for (int j = 0; j < 8; j++) {
            float4 v = R[j];
            int kb = 16 * j + 4 * q;
            float4 wx = *(const float4*)(sW1p + kb);
            float4 wy = *(const float4*)(sW1p + 128 + kb);
            float4 wz = *(const float4*)(sW1p + 256 + kb);
            float h0 = fmaxf(v.x + rx * wx.x + ry * wy.x + rz * wz.x, 0.f);
            float h1 = fmaxf(v.y + rx * wx.y + ry * wy.y + rz * wz.y, 0.f);
            float h2 = fmaxf(v.z + rx * wx.z + ry * wy.z + rz * wz.z, 0.f);
            float h3 = fmaxf(v.w + rx * wx.w + ry * wy.w + rz * wz.w, 0.f);
            uint2 o;
            o.x = packh2(h0, h1);
            o.y = packh2(h2, h3);
            *(uint2*)(sTw + rloc * 68 + j * 8 + q * 2) = o;
        }
        if (tid < 128) sColB[cur * 128 + tid] = pcol;

        // ---- prefetch(t+1) -> regs (hidden under GEMM) ----
        {
            int nt = tile + gridDim.x;
            int pb = (nt < NTILES ? nt : 0) * 128;
            int pr = g_er[pb + rloc];
            int pc = g_ec[pb + rloc];
            rx = pos[3 * pr    ] - pos[3 * pc    ];
            ry = pos[3 * pr + 1] - pos[3 * pc + 1];
            rz = pos[3 * pr + 2] - pos[3 * pc + 2];
            const float4* tp = (const float4*)(g_t + (size_t)pr * 128);
#pragma unroll
            for (int j = 0; j < 8; j++) R[j] = tp[j * 4 + q];
            if (tid < 128) pcol = g_ec[pb + tid];
        }
        __syncthreads();   // [A] sT/sColB visible; sC free (run-max done)

        // ---- GEMM(t): 8 k16-steps, per warp 2 m16 x 4 n8 ----
        float acc[2][4][4];
#pragma unroll
        for (int mb = 0; mb < 2; mb++)
#pragma unroll
            for (int nb = 0; nb < 4; nb++)
#pragma unroll
                for (int r = 0; r < 4; r++) acc[mb][nb][r] = 0.f;

#pragma unroll
        for (int s = 0; s < 8; s++) {
            uint32_t A0[4], A1[4];
            ldsm_x4(A0, aAddr0 + s * 32);
            ldsm_x4(A1, aAddr1 + s * 32);
#pragma unroll
            for (int nb = 0; nb < 4; nb++) {
                uint2 bv = sBf[(s * 16 + wc * 4 + nb) * 32 + lane];
                mma_fp16(acc[0][nb], A0, bv.x, bv.y);
                mma_fp16(acc[1][nb], A1, bv.x, bv.y);
            }
        }

        // ---- epilogue: acc -> sC transposed, +b2 (pitch 132: conflict-free) ----
#pragma unroll
        for (int mb = 0; mb < 2; mb++) {
#pragma unroll
            for (int nb = 0; nb < 4; nb++) {
#pragma unroll
                for (int r = 0; r < 4; r++) {
                    int row = wr * 32 + mb * 16 + nn + ((r >> 1) ? 8 : 0);
                    int col = wc * 32 + nb * 8 + q * 2 + (r & 1);
                    sC[col * SC_PITCH + row] = acc[mb][nb][r] + sb2[col];
                }
            }
        }
        __syncthreads();   // [B] sC visible; GEMM's sT reads done

        // ---- run-max(t): 4 segs of 32 rows; float4 sC reads, int4 sCol ----
        {
            int col = tid & 127;
            int r0  = (tid >> 7) * 32;
            const float* cbase = sC + col * SC_PITCH + r0;   // 16B-aligned (132%4==0, r0%32==0)
            const int4* colv = (const int4*)(sColB + cur * 128 + r0);
            int curc = sColB[cur * 128 + r0];
            float m = -3.402823466e+38f;
#pragma unroll
            for (int m4 = 0; m4 < 8; m4++) {
                int4  c4 = colv[m4];
                float4 v4 = *(const float4*)(cbase + 4 * m4);
                if (c4.x != curc) { atomicMax(&g_seg[(size_t)curc * 128 + col], fmap(m)); curc = c4.x; m = v4.x; }
                else m = fmaxf(m, v4.x);
                if (c4.y != curc) { atomicMax(&g_seg[(size_t)curc * 128 + col], fmap(m)); curc = c4.y; m = v4.y; }
                else m = fmaxf(m, v4.y);
                if (c4.z != curc) { atomicMax(&g_seg[(size_t)curc * 128 + col], fmap(m)); curc = c4.z; m = v4.z; }
                else m = fmaxf(m, v4.z);
                if (c4.w != curc) { atomicMax(&g_seg[(size_t)curc * 128 + col], fmap(m)); curc = c4.w; m = v4.w; }
                else m = fmaxf(m, v4.w);
            }
            atomicMax(&g_seg[(size_t)curc * 128 + col], fmap(m));
        }
    }
}

// ---------------------------------------------------------------------------
__global__ void finalize(float* __restrict__ out) {      // LAUNCH #5
    int i = blockIdx.x * blockDim.x + threadIdx.x;       // uint4 index
    if (i < N_NODES * 32) {
        uint4 u = ((const uint4*)g_seg)[i];
        float4 o = *(float4*)(out + 4 * i);
        o.x += (u.x == SENT) ? 0.f : funmap(u.x);
        o.y += (u.y == SENT) ? 0.f : funmap(u.y);
        o.z += (u.z == SENT) ? 0.f : funmap(u.z);
        o.w += (u.w == SENT) ? 0.f : funmap(u.w);
        *(float4*)(out + 4 * i) = o;
    }
}

// ---------------------------------------------------------------------------
extern "C" void kernel_launch(void* const* d_in, const int* in_sizes, int n_in,
                              void* d_out, int out_size)
{
    const float* x   = (const float*)d_in[0];
    const float* pos = (const float*)d_in[1];
    const int*   ei  = (const int*)  d_in[2];
    const float* W1  = (const float*)d_in[3];
    const float* b1  = (const float*)d_in[4];
    const float* W2  = (const float*)d_in[5];
    const float* b2  = (const float*)d_in[6];
    const float* Wr  = (const float*)d_in[7];
    const float* br  = (const float*)d_in[8];
    float* out = (float*)d_out;

    const int NODE_SMEM = (64 * 128 + 16 * 256) * 4;

    cudaFuncSetAttribute(pre_kernel,  cudaFuncAttributeMaxDynamicSharedMemorySize, NODE_SMEM);
    cudaFuncSetAttribute(edge_kernel, cudaFuncAttributeMaxDynamicSharedMemorySize, EDGE_SMEM_BYTES);

    int nsm = 148;
    cudaDeviceGetAttribute(&nsm, cudaDevAttrMultiProcessorCount, 0);

    pre_kernel<<<PRE_BLKS, 256, NODE_SMEM>>>(x, W1, b1, Wr, br, out, ei);   // 1
    scan1_kernel<<<NBLK, 1024>>>();                                          // 2
    scatter_kernel<<<(E_EDGES + 1023) / 1024, 1024>>>(ei);                   // 3
    edge_kernel<<<nsm, 512, EDGE_SMEM_BYTES>>>(pos, W1, W2, b2);             // 4
    finalize<<<(N_NODES * 32 + 255) / 256, 256>>>(out);                      // 5
}

// round 17
// speedup vs baseline: 1.4669x; 1.2035x over previous
#include <cuda_runtime.h>
#include <cuda_fp16.h>
#include <cstdint>

#define N_NODES 50000
#define E_EDGES 1600000
#define NTILES  (E_EDGES / 128)   // 12500 exact
#define NBLK    ((N_NODES + 1023) / 1024)   // 49

#define NODE_BLKS 391    // ceil(50000/128)
#define HIST_BLKS 3125   // E/512
#define INITV_BLKS 3125  // N*128/4 uint4 / 512 thr
#define PRE_BLKS (NODE_BLKS + HIST_BLKS + INITV_BLKS)
#define PRE_SMEM_BYTES (8704 * 4 + 8192 * 8)   // sX (fp16 128x136) + W frags = 100352

// ---------------- device scratch ----------------
__device__ float    g_t[(size_t)N_NODES * 128];     // x@W1a + b1 (fp32)
__device__ unsigned g_seg[(size_t)N_NODES * 128];   // order-preserving max
__device__ unsigned g_hist[N_NODES];                // invariant: zero at kernel_launch entry
__device__ unsigned g_cursor[N_NODES];
__device__ unsigned g_bsum[64];
__device__ int      g_er[E_EDGES];                  // rows, sorted by col
__device__ int      g_ec[E_EDGES];                  // cols, sorted

#define SENT 0x007FFFFFu   // fmap(-inf)

__device__ __forceinline__ unsigned fmap(float f) {
    unsigned u = __float_as_uint(f);
    return (u & 0x80000000u) ? ~u : (u | 0x80000000u);
}
__device__ __forceinline__ float funmap(unsigned u) {
    return __uint_as_float((u & 0x80000000u) ? (u ^ 0x80000000u) : ~u);
}
__device__ __forceinline__ void mma_fp16(float* d, const uint32_t* a, uint32_t b0, uint32_t b1) {
    asm volatile("mma.sync.aligned.m16n8k16.row.col.f32.f16.f16.f32 "
        "{%0,%1,%2,%3}, {%4,%5,%6,%7}, {%8,%9}, {%0,%1,%2,%3};"
        : "+f"(d[0]), "+f"(d[1]), "+f"(d[2]), "+f"(d[3])
        : "r"(a[0]), "r"(a[1]), "r"(a[2]), "r"(a[3]), "r"(b0), "r"(b1));
}
__device__ __forceinline__ uint32_t packh2(float a, float b) {
    __half2 h = __floats2half2_rn(a, b);
    return *(uint32_t*)&h;
}
__device__ __forceinline__ uint32_t smem_u32(const void* p) {
    uint32_t a;
    asm("{ .reg .u64 t; cvta.to.shared.u64 t, %1; cvt.u32.u64 %0, t; }" : "=r"(a) : "l"(p));
    return a;
}
__device__ __forceinline__ void ldsm_x4(uint32_t* r, uint32_t addr) {
    asm volatile("ldmatrix.sync.aligned.m8n8.x4.shared.b16 {%0,%1,%2,%3}, [%4];"
        : "=r"(r[0]), "=r"(r[1]), "=r"(r[2]), "=r"(r[3]) : "r"(addr));
}

// ---------------------------------------------------------------------------
// pre_kernel (512 thr)  LAUNCH #1:
//   blocks [0, 391)    : node GEMM via fp16 HMMA: t = x@W1a+b1 (fp32 out),
//                        out = x@Wr+br
//   blocks [391, 3516) : edge-dst histogram
//   blocks [3516, 6641): g_seg = SENT (uint4)
// ---------------------------------------------------------------------------
__global__ void __launch_bounds__(512) pre_kernel(
    const float* __restrict__ x, const float* __restrict__ W1,
    const float* __restrict__ b1, const float* __restrict__ Wr,
    const float* __restrict__ br, float* __restrict__ out,
    const int* __restrict__ ei)
{
    int tid = threadIdx.x;
    int b   = blockIdx.x;

    if (b >= NODE_BLKS) {
        if (b < NODE_BLKS + HIST_BLKS) {
            int e = (b - NODE_BLKS) * 512 + tid;
            atomicAdd(&g_hist[ei[E_EDGES + e]], 1u);
        } else {
            int i = (b - NODE_BLKS - HIST_BLKS) * 512 + tid;   // uint4 index
            uint4 s = make_uint4(SENT, SENT, SENT, SENT);
            ((uint4*)g_seg)[i] = s;
        }
        return;
    }

    // ---- node GEMM: 128 nodes x 256 outs, fp16 HMMA ----
    extern __shared__ float sm[];
    uint32_t* sXw = (uint32_t*)sm;             // fp16 x tile, pitch 68 words
    uint2*    sWf = (uint2*)(sm + 8704);       // W1a|Wr fragments (8192 uint2)

    int base = b * 128;
    int wid  = tid >> 5;
    int lane = tid & 31;
    int q    = lane & 3;
    int nn   = lane >> 2;
    int wr   = wid & 3;      // rows wr*32..+31
    int wc   = wid >> 2;     // cols wc*64..+63

    // W fragments: n 0..255 = W1a | Wr
    for (int i = tid; i < 8192; i += 512) {
        int ln = i & 31, nbg = (i >> 5) & 31, s = i >> 10;
        int qq = ln & 3, nni = ln >> 2;
        int n = nbg * 8 + nni, k = s * 16 + qq * 2;
        float w00, w01, w10, w11;
        if (n < 128) {
            w00 = W1[k * 128 + n];       w01 = W1[(k + 1) * 128 + n];
            w10 = W1[(k + 8) * 128 + n]; w11 = W1[(k + 9) * 128 + n];
        } else {
            int n2 = n - 128;
            w00 = Wr[k * 128 + n2];       w01 = Wr[(k + 1) * 128 + n2];
            w10 = Wr[(k + 8) * 128 + n2]; w11 = Wr[(k + 9) * 128 + n2];
        }
        uint2 v;
        v.x = packh2(w00, w01);
        v.y = packh2(w10, w11);
        sWf[i] = v;
    }

    // x tile -> fp16 sX (zero-pad past N)
    {
        int row = tid >> 2, q4 = tid & 3;
        int node = base + row;
        const float4* xp = (const float4*)(x + (size_t)node * 128);
#pragma unroll
        for (int j = 0; j < 8; j++) {
            uint2 o = make_uint2(0u, 0u);
            if (node < N_NODES) {
                float4 v = xp[j * 4 + q4];
                o.x = packh2(v.x, v.y);
                o.y = packh2(v.z, v.w);
            }
            *(uint2*)(sXw + row * 68 + j * 8 + q4 * 2) = o;
        }
    }
    __syncthreads();

    uint32_t stbase = smem_u32(sXw);
    int lrow = wr * 32 + (lane & 15);
    int lk   = (lane >> 4) << 3;
    uint32_t aAddr0 = stbase + (uint32_t)((lrow       * 136 + lk) * 2);
    uint32_t aAddr1 = stbase + (uint32_t)(((lrow + 16) * 136 + lk) * 2);

    float acc[2][8][4];
#pragma unroll
    for (int mb = 0; mb < 2; mb++)
#pragma unroll
        for (int nb = 0; nb < 8; nb++)
#pragma unroll
            for (int r = 0; r < 4; r++) acc[mb][nb][r] = 0.f;

#pragma unroll
    for (int s = 0; s < 8; s++) {
        uint32_t A0[4], A1[4];
        ldsm_x4(A0, aAddr0 + s * 32);
        ldsm_x4(A1, aAddr1 + s * 32);
#pragma unroll
        for (int nb = 0; nb < 8; nb++) {
            uint2 bv = sWf[(s * 32 + wc * 8 + nb) * 32 + lane];
            mma_fp16(acc[0][nb], A0, bv.x, bv.y);
            mma_fp16(acc[1][nb], A1, bv.x, bv.y);
        }
    }

    // epilogue: +bias, float2 stores (adjacent cols q*2, q*2+1)
#pragma unroll
    for (int mb = 0; mb < 2; mb++) {
#pragma unroll
        for (int nb = 0; nb < 8; nb++) {
#pragma unroll
            for (int rh = 0; rh < 2; rh++) {
                int row = wr * 32 + mb * 16 + nn + 8 * rh;
                int node = base + row;
                if (node >= N_NODES) continue;
                int col = wc * 64 + nb * 8 + q * 2;
                float v0 = acc[mb][nb][rh * 2];
                float v1 = acc[mb][nb][rh * 2 + 1];
                if (col < 128) {
                    float2 o = make_float2(v0 + __ldg(b1 + col), v1 + __ldg(b1 + col + 1));
                    *(float2*)(g_t + (size_t)node * 128 + col) = o;
                } else {
                    int c2 = col - 128;
                    float2 o = make_float2(v0 + __ldg(br + c2), v1 + __ldg(br + c2 + 1));
                    *(float2*)(out + (size_t)node * 128 + c2) = o;
                }
            }
        }
    }
}

// block-local exclusive scan; re-zeroes g_hist        LAUNCH #2
__global__ void scan1_kernel() {
    __shared__ unsigned s[1024];
    int tid = threadIdx.x;
    int gid = blockIdx.x * 1024 + tid;
    unsigned v = (gid < N_NODES) ? g_hist[gid] : 0u;
    s[tid] = v; __syncthreads();
    for (int off = 1; off < 1024; off <<= 1) {
        unsigned t = (tid >= off) ? s[tid - off] : 0u;
        __syncthreads();
        s[tid] += t;
        __syncthreads();
    }
    if (gid < N_NODES) {
        g_cursor[gid] = s[tid] - v;
        g_hist[gid] = 0u;
    }
    if (tid == 1023) g_bsum[blockIdx.x] = s[1023];
}

// scatter with local bsum scan                        LAUNCH #3
__global__ void scatter_kernel(const int* __restrict__ ei) {
    __shared__ unsigned sB[64];
    int tid = threadIdx.x;
    if (tid < NBLK) sB[tid] = g_bsum[tid];
    __syncthreads();
    if (tid == 0) {
        unsigned c = 0;
#pragma unroll 1
        for (int b = 0; b < NBLK; b++) { unsigned t = sB[b]; sB[b] = c; c += t; }
    }
    __syncthreads();
    int e = blockIdx.x * blockDim.x + tid;
    if (e < E_EDGES) {
        int c = ei[E_EDGES + e];
        unsigned p = atomicAdd(&g_cursor[c], 1u) + sB[c >> 10];
        g_er[p] = ei[e];
        g_ec[p] = c;
    }
}

// ---------------------------------------------------------------------------
// edge kernel (512 thr, software-pipelined)
//   B fragments stored as uint4 (nb pairs) -> half the B LDS instructions
//   Everything else identical to R14 (sC pitch 132).
//                                                     LAUNCH #4  <-- PROFILED
// ---------------------------------------------------------------------------
#define SC_PITCH 132
#define W1P_F  0
#define B2_F   384
#define COLB_F 512                  // 2 x 128 ints (double-buffered)
#define SB_F   768                  // 8192 floats = 2048 uint4 fragments
#define SC_F   (SB_F + 8192)        // 8960: 128 x 132 fp32 = 16896 floats
#define ST_F   (SC_F + 16896)       // 25856: fp16 128 x 136 halves = 8704 floats
#define EDGE_SMEM_F (ST_F + 8704)   // 34560 floats = 138240 B
#define EDGE_SMEM_BYTES (EDGE_SMEM_F * 4)

__global__ void __launch_bounds__(512, 1) edge_kernel(
    const float* __restrict__ pos, const float* __restrict__ W1,
    const float* __restrict__ W2, const float* __restrict__ b2)
{
    extern __shared__ float sm[];
    float*    sW1p  = sm + W1P_F;
    float*    sb2   = sm + B2_F;
    int*      sColB = (int*)(sm + COLB_F);
    uint4*    sBf4  = (uint4*)(sm + SB_F);
    float*    sC    = sm + SC_F;                 // [col][row] pitch 132
    uint32_t* sTw   = (uint32_t*)(sm + ST_F);    // fp16 tile, pitch 68 words

    int tid  = threadIdx.x;
    int wid  = tid >> 5;
    int lane = tid & 31;
    int q    = lane & 3;
    int nn   = lane >> 2;
    int wr   = wid & 3;
    int wc   = wid >> 2;

    // one-time: W2 fp16 fragments (uint4: nb pairs), W1p, b2
    for (int i = tid; i < 2048; i += 512) {
        int ln = i & 31, g = i >> 5;
        int nbp = g & 1, wcg = (g >> 1) & 3, s = g >> 3;
        int qq = ln & 3, nni = ln >> 2;
        int k = s * 16 + qq * 2;
        int n0 = (wcg * 4 + nbp * 2) * 8 + nni;
        int n1 = n0 + 8;
        uint4 v;
        v.x = packh2(W2[k * 128 + n0],       W2[(k + 1) * 128 + n0]);
        v.y = packh2(W2[(k + 8) * 128 + n0], W2[(k + 9) * 128 + n0]);
        v.z = packh2(W2[k * 128 + n1],       W2[(k + 1) * 128 + n1]);
        v.w = packh2(W2[(k + 8) * 128 + n1], W2[(k + 9) * 128 + n1]);
        sBf4[i] = v;
    }
    for (int f = tid; f < 384; f += 512) sW1p[f] = W1[128 * 128 + f];
    if (tid < 128) sb2[tid] = b2[tid];
    __syncthreads();   // preload visible before stage(tile0)

    // ldmatrix per-lane addresses
    uint32_t stbase = smem_u32(sTw);
    int lrow = wr * 32 + (lane & 15);
    int lk   = (lane >> 4) << 3;
    uint32_t aAddr0 = stbase + (uint32_t)((lrow       * 136 + lk) * 2);
    uint32_t aAddr1 = stbase + (uint32_t)(((lrow + 16) * 136 + lk) * 2);

    int rloc = wid * 8 + nn;                     // row this thread stages

    // ---- prologue: prefetch tile0 into regs (fp32) ----
    int tile = blockIdx.x;
    float4 R[8];
    float rx = 0.f, ry = 0.f, rz = 0.f;
    int pcol = 0;
    {
        int pb = (tile < NTILES ? tile : 0) * 128;
        int pr = g_er[pb + rloc];
        int pc = g_ec[pb + rloc];
        rx = pos[3 * pr    ] - pos[3 * pc    ];
        ry = pos[3 * pr + 1] - pos[3 * pc + 1];
        rz = pos[3 * pr + 2] - pos[3 * pc + 2];
        const float4* tp = (const float4*)(g_t + (size_t)pr * 128);
#pragma unroll
        for (int j = 0; j < 8; j++) R[j] = tp[j * 4 + q];
        if (tid < 128) pcol = g_ec[pb + tid];
    }

    int cur = 0;
    for (; tile < NTILES; tile += gridDim.x, cur ^= 1) {
        // ---- stage(t): regs -> sT (single fp16 quantization here) ----
#pragma unroll
        for (int j = 0; j < 8; j++) {
            float4 v = R[j];
            int kb = 16 * j + 4 * q;
            float4 wx = *(const float4*)(sW1p + kb);
            float4 wy = *(const float4*)(sW1p + 128 + kb);
            float4 wz = *(const float4*)(sW1p + 256 + kb);
            float h0 = fmaxf(v.x + rx * wx.x + ry * wy.x + rz * wz.x, 0.f);
            float h1 = fmaxf(v.y + rx * wx.y + ry * wy.y + rz * wz.y, 0.f);
            float h2 = fmaxf(v.z + rx * wx.z + ry * wy.z + rz * wz.z, 0.f);
            float h3 = fmaxf(v.w + rx * wx.w + ry * wy.w + rz * wz.w, 0.f);
            uint2 o;
            o.x = packh2(h0, h1);
            o.y = packh2(h2, h3);
            *(uint2*)(sTw + rloc * 68 + j * 8 + q * 2) = o;
        }
        if (tid < 128) sColB[cur * 128 + tid] = pcol;

        // ---- prefetch(t+1) -> regs (hidden under GEMM) ----
        {
            int nt = tile + gridDim.x;
            int pb = (nt < NTILES ? nt : 0) * 128;
            int pr = g_er[pb + rloc];
            int pc = g_ec[pb + rloc];
            rx = pos[3 * pr    ] - pos[3 * pc    ];
            ry = pos[3 * pr + 1] - pos[3 * pc + 1];
            rz = pos[3 * pr + 2] - pos[3 * pc + 2];
            const float4* tp = (const float4*)(g_t + (size_t)pr * 128);
#pragma unroll
            for (int j = 0; j < 8; j++) R[j] = tp[j * 4 + q];
            if (tid < 128) pcol = g_ec[pb + tid];
        }
        __syncthreads();   // [A] sT/sColB visible; sC free (run-max done)

        // ---- GEMM(t): 8 k16-steps, per warp 2 m16 x 4 n8 (B via uint4) ----
        float acc[2][4][4];
#pragma unroll
        for (int mb = 0; mb < 2; mb++)
#pragma unroll
            for (int nb = 0; nb < 4; nb++)
#pragma unroll
                for (int r = 0; r < 4; r++) acc[mb][nb][r] = 0.f;

#pragma unroll
        for (int s = 0; s < 8; s++) {
            uint32_t A0[4], A1[4];
            ldsm_x4(A0, aAddr0 + s * 32);
            ldsm_x4(A1, aAddr1 + s * 32);
#pragma unroll
            for (int nbp = 0; nbp < 2; nbp++) {
                uint4 bv = sBf4[(s * 8 + wc * 2 + nbp) * 32 + lane];
                mma_fp16(acc[0][nbp * 2],     A0, bv.x, bv.y);
                mma_fp16(acc[1][nbp * 2],     A1, bv.x, bv.y);
                mma_fp16(acc[0][nbp * 2 + 1], A0, bv.z, bv.w);
                mma_fp16(acc[1][nbp * 2 + 1], A1, bv.z, bv.w);
            }
        }

        // ---- epilogue: acc -> sC transposed, +b2 (pitch 132: conflict-free) ----
#pragma unroll
        for (int mb = 0; mb < 2; mb++) {
#pragma unroll
            for (int nb = 0; nb < 4; nb++) {
#pragma unroll
                for (int r = 0; r < 4; r++) {
                    int row = wr * 32 + mb * 16 + nn + ((r >> 1) ? 8 : 0);
                    int col = wc * 32 + nb * 8 + q * 2 + (r & 1);
                    sC[col * SC_PITCH + row] = acc[mb][nb][r] + sb2[col];
                }
            }
        }
        __syncthreads();   // [B] sC visible; GEMM's sT reads done

        // ---- run-max(t): 4 segs of 32 rows; float4 sC reads, int4 sCol ----
        {
            int col = tid & 127;
            int r0  = (tid >> 7) * 32;
            const float* cbase = sC + col * SC_PITCH + r0;
            const int4* colv = (const int4*)(sColB + cur * 128 + r0);
            int curc = sColB[cur * 128 + r0];
            float m = -3.402823466e+38f;
#pragma unroll
            for (int m4 = 0; m4 < 8; m4++) {
                int4  c4 = colv[m4];
                float4 v4 = *(const float4*)(cbase + 4 * m4);
                if (c4.x != curc) { atomicMax(&g_seg[(size_t)curc * 128 + col], fmap(m)); curc = c4.x; m = v4.x; }
                else m = fmaxf(m, v4.x);
                if (c4.y != curc) { atomicMax(&g_seg[(size_t)curc * 128 + col], fmap(m)); curc = c4.y; m = v4.y; }
                else m = fmaxf(m, v4.y);
                if (c4.z != curc) { atomicMax(&g_seg[(size_t)curc * 128 + col], fmap(m)); curc = c4.z; m = v4.z; }
                else m = fmaxf(m, v4.z);
                if (c4.w != curc) { atomicMax(&g_seg[(size_t)curc * 128 + col], fmap(m)); curc = c4.w; m = v4.w; }
                else m = fmaxf(m, v4.w);
            }
            atomicMax(&g_seg[(size_t)curc * 128 + col], fmap(m));
        }
    }
}

// ---------------------------------------------------------------------------
__global__ void finalize(float* __restrict__ out) {      // LAUNCH #5
    int i = blockIdx.x * blockDim.x + threadIdx.x;       // uint4 index
    if (i < N_NODES * 32) {
        uint4 u = ((const uint4*)g_seg)[i];
        float4 o = *(float4*)(out + 4 * i);
        o.x += (u.x == SENT) ? 0.f : funmap(u.x);
        o.y += (u.y == SENT) ? 0.f : funmap(u.y);
        o.z += (u.z == SENT) ? 0.f : funmap(u.z);
        o.w += (u.w == SENT) ? 0.f : funmap(u.w);
        *(float4*)(out + 4 * i) = o;
    }
}

// ---------------------------------------------------------------------------
extern "C" void kernel_launch(void* const* d_in, const int* in_sizes, int n_in,
                              void* d_out, int out_size)
{
    const float* x   = (const float*)d_in[0];
    const float* pos = (const float*)d_in[1];
    const int*   ei  = (const int*)  d_in[2];
    const float* W1  = (const float*)d_in[3];
    const float* b1  = (const float*)d_in[4];
    const float* W2  = (const float*)d_in[5];
    const float* b2  = (const float*)d_in[6];
    const float* Wr  = (const float*)d_in[7];
    const float* br  = (const float*)d_in[8];
    float* out = (float*)d_out;

    cudaFuncSetAttribute(pre_kernel,  cudaFuncAttributeMaxDynamicSharedMemorySize, PRE_SMEM_BYTES);
    cudaFuncSetAttribute(edge_kernel, cudaFuncAttributeMaxDynamicSharedMemorySize, EDGE_SMEM_BYTES);

    int nsm = 148;
    cudaDeviceGetAttribute(&nsm, cudaDevAttrMultiProcessorCount, 0);

    pre_kernel<<<PRE_BLKS, 512, PRE_SMEM_BYTES>>>(x, W1, b1, Wr, br, out, ei);  // 1
    scan1_kernel<<<NBLK, 1024>>>();                                              // 2
    scatter_kernel<<<(E_EDGES + 1023) / 1024, 1024>>>(ei);                       // 3
    edge_kernel<<<nsm, 512, EDGE_SMEM_BYTES>>>(pos, W1, W2, b2);                 // 4
    finalize<<<(N_NODES * 32 + 255) / 256, 256>>>(out);                          // 5
}